// round 15
// baseline (speedup 1.0000x reference)
#include <cuda_runtime.h>
#include <cuda_fp16.h>
#include <stdint.h>
#include <math.h>

#define BQ   4096
#define NSEG 100
#define DIM  4096
#define HID  128
#define TOPK 10
#define NSLICE 128
#define DCH  (DIM / NSLICE)   /* 32 */
#define KSPLIT 8
#define NBQ  2                /* queries per block in k3 */

__device__ float g_qhp[KSPLIT][BQ * HID];
__device__ float g_sh[NSEG * HID];
__device__ float g_imp[NSEG];
__device__ float g_cs[NSEG];
__device__ float g_p1[NSLICE * NSEG * HID];
__device__ float g_p2[NSLICE * NSEG * HID];
__device__ __align__(16) unsigned short g_wh0[HID * DIM];
__device__ __align__(16) unsigned short g_wh1[HID * DIM];

__device__ __forceinline__ float gelu_f(float x) {
    return 0.5f * x * (1.0f + erff(x * 0.70710678118654752440f));
}
__device__ __forceinline__ float gelu_fast(float x) {
    float z = 0.70710678118654752440f * x;
    float a = fabsf(z);
    float t = __fdividef(1.0f, fmaf(0.3275911f, a, 1.0f));
    float poly = t * fmaf(t, fmaf(t, fmaf(t, fmaf(t, 1.061405429f, -1.453152027f),
                                          1.421413741f), -0.284496736f), 0.254829592f);
    float e = __expf(-z * z);
    float erfz = copysignf(fmaf(-poly, e, 1.0f), z);
    return fmaf(0.5f * x, erfz, 0.5f * x);
}
__device__ __forceinline__ float sigmoid_f(float x) { return 1.0f / (1.0f + expf(-x)); }

__device__ __forceinline__ void cp16(unsigned int s, const void* g) {
    asm volatile("cp.async.cg.shared.global [%0], [%1], 16;" :: "r"(s), "l"(g));
}
__device__ __forceinline__ void cp_commit() { asm volatile("cp.async.commit_group;"); }
__device__ __forceinline__ void cp_wait0()  { asm volatile("cp.async.wait_group 0;"); }

__device__ __forceinline__ void mma16(float* c, const unsigned int* a, const unsigned int* b) {
    asm volatile(
        "mma.sync.aligned.m16n8k16.row.col.f32.f16.f16.f32 "
        "{%0,%1,%2,%3}, {%4,%5,%6,%7}, {%8,%9}, {%0,%1,%2,%3};"
        : "+f"(c[0]), "+f"(c[1]), "+f"(c[2]), "+f"(c[3])
        : "r"(a[0]), "r"(a[1]), "r"(a[2]), "r"(a[3]), "r"(b[0]), "r"(b[1]));
}
__device__ __forceinline__ void split_h2(float2 v, unsigned int& hi, unsigned int& lo) {
    __half2 h = __floats2half2_rn(v.x, v.y);
    float2 hf = __half22float2(h);
    __half2 l = __floats2half2_rn(v.x - hf.x, v.y - hf.y);
    hi = *(unsigned int*)&h;
    lo = *(unsigned int*)&l;
}
__device__ __forceinline__ unsigned short h_hi(float x, float& rem) {
    __half h = __float2half_rn(x);
    rem = x - __half2float(h);
    return *(unsigned short*)&h;
}

// ---- kernel 1a: segment partials + (by==0) weight transpose/split ----
// grid (NSLICE=128, 10), 128 threads.
__global__ __launch_bounds__(128) void k1a_part(const float* __restrict__ seg,
                                                const float* __restrict__ iw1,
                                                const float* __restrict__ rw1) {
    int h = threadIdx.x, d0 = blockIdx.x * DCH, n0 = blockIdx.y * 10;

    if (blockIdx.y == 0) {
        for (int k4 = 0; k4 < DCH; k4 += 4) {
            float r0, r1, r2, r3;
            unsigned short a0 = h_hi(rw1[(size_t)(d0 + k4 + 0) * HID + h], r0);
            unsigned short a1 = h_hi(rw1[(size_t)(d0 + k4 + 1) * HID + h], r1);
            unsigned short a2 = h_hi(rw1[(size_t)(d0 + k4 + 2) * HID + h], r2);
            unsigned short a3 = h_hi(rw1[(size_t)(d0 + k4 + 3) * HID + h], r3);
            float d;
            ushort4 hv = make_ushort4(a0, a1, a2, a3);
            ushort4 lv = make_ushort4(h_hi(r0, d), h_hi(r1, d), h_hi(r2, d), h_hi(r3, d));
            *(ushort4*)(&g_wh0[(size_t)h * DIM + d0 + k4]) = hv;
            *(ushort4*)(&g_wh1[(size_t)h * DIM + d0 + k4]) = lv;
        }
    }

    __shared__ float segs[10][DCH];
    for (int i = h; i < 10 * DCH; i += 128)
        segs[i / DCH][i % DCH] = seg[(size_t)(n0 + i / DCH) * DIM + d0 + (i % DCH)];
    __syncthreads();
    float a1[10], a2[10];
#pragma unroll
    for (int n = 0; n < 10; n++) { a1[n] = 0.f; a2[n] = 0.f; }
    const float* w1p = iw1 + (size_t)d0 * HID + h;
    const float* w2p = rw1 + (size_t)(DIM + d0) * HID + h;
#pragma unroll 4
    for (int dd = 0; dd < DCH; dd++) {
        float w1 = w1p[(size_t)dd * HID], w2 = w2p[(size_t)dd * HID];
#pragma unroll
        for (int n = 0; n < 10; n++) {
            a1[n] = fmaf(segs[n][dd], w1, a1[n]);
            a2[n] = fmaf(segs[n][dd], w2, a2[n]);
        }
    }
#pragma unroll
    for (int n = 0; n < 10; n++) {
        g_p1[(blockIdx.x * NSEG + n0 + n) * HID + h] = a1[n];
        g_p2[(blockIdx.x * NSEG + n0 + n) * HID + h] = a2[n];
    }
}

// ---- kernel 2: mma blocks 0..255 + k1b blocks 256..355 ----
#define QS_STRIDE 36
#define WH_STRIDE 40
#define QS_BUF (128 * QS_STRIDE)
#define WH_BUF (128 * WH_STRIDE)
#define K2_SMEM (2 * QS_BUF * 4 + 4 * WH_BUF * 2)
__global__ __launch_bounds__(256, 2) void k2_mma(const float* __restrict__ query,
                                                 const int* __restrict__ positions,
                                                 const float* __restrict__ ib1,
                                                 const float* __restrict__ iw2,
                                                 const float* __restrict__ ib2) {
    int tid = threadIdx.x, lane = tid & 31, wid = tid >> 5;

    if (blockIdx.x >= 256) {
        int n = blockIdx.x - 256;
        __shared__ float red[4];
        float t = 0.f;
        if (tid < 128) {
            int h = tid;
            float s1 = 0.f, s2 = 0.f;
#pragma unroll 16
            for (int s = 0; s < NSLICE; s++) {
                s1 += g_p1[(s * NSEG + n) * HID + h];
                s2 += g_p2[(s * NSEG + n) * HID + h];
            }
            g_sh[n * HID + h] = s2;
            t = gelu_f(s1 + ib1[h]) * iw2[h];
#pragma unroll
            for (int off = 16; off >= 1; off >>= 1) t += __shfl_xor_sync(0xffffffffu, t, off);
            if (lane == 0) red[wid] = t;
        }
        __syncthreads();
        if (tid == 0) {
            float imp = sigmoid_f(red[0] + red[1] + red[2] + red[3] + ib2[0]);
            g_imp[n] = imp;
            g_cs[n] = imp * (0.5f + 0.5f * powf(0.95f, (float)(NSEG - 1 - positions[n])));
        }
        return;
    }

    extern __shared__ float sm[];
    float* qs = sm;
    unsigned short* wh = (unsigned short*)(sm + 2 * QS_BUF);

    int wm = wid & 3, wn = wid >> 2;
    int m0 = (blockIdx.x & 31) * 128;
    int ksp = blockIdx.x >> 5;
    int kbase = ksp * (DIM / KSPLIT);

    unsigned int qs_b = (unsigned int)__cvta_generic_to_shared(qs);
    unsigned int wh_b = (unsigned int)__cvta_generic_to_shared(wh);

    float c[2][8][4];
#pragma unroll
    for (int mt = 0; mt < 2; mt++)
#pragma unroll
        for (int nt = 0; nt < 8; nt++)
#pragma unroll
            for (int p = 0; p < 4; p++) c[mt][nt][p] = 0.f;

    auto issue = [&](int buf, int kc) {
#pragma unroll
        for (int j = 0; j < 4; j++) {
            int i = tid + j * 256;
            int row = i >> 3, g = i & 7;
            cp16(qs_b + (unsigned int)(buf * QS_BUF * 4 + row * (QS_STRIDE * 4) + g * 16),
                 query + (size_t)(m0 + row) * DIM + kc + g * 4);
        }
#pragma unroll
        for (int j = 0; j < 2; j++) {
            int i = tid + j * 256;
            int n = i >> 2, g = i & 3;
            cp16(wh_b + (unsigned int)((buf * 2 + 0) * WH_BUF * 2 + n * (WH_STRIDE * 2) + g * 16),
                 g_wh0 + (size_t)n * DIM + kc + g * 8);
        }
#pragma unroll
        for (int j = 0; j < 2; j++) {
            int i = tid + j * 256;
            int n = i >> 2, g = i & 3;
            cp16(wh_b + (unsigned int)((buf * 2 + 1) * WH_BUF * 2 + n * (WH_STRIDE * 2) + g * 16),
                 g_wh1 + (size_t)n * DIM + kc + g * 8);
        }
        cp_commit();
    };

    issue(0, kbase);
    cp_wait0();
    __syncthreads();

    int r0 = lane >> 2;
    int cq = (lane & 3) * 2;
    int bn = wn * 64 + (lane >> 2);
    int bw = lane & 3;

    const int NCH = (DIM / KSPLIT) / 32;
    for (int ch = 0; ch < NCH; ch++) {
        int cur = ch & 1;
        if (ch + 1 < NCH) issue(cur ^ 1, kbase + (ch + 1) * 32);

        const float* qc = qs + cur * QS_BUF;
        const unsigned int* wh0 = (const unsigned int*)(wh + (cur * 2 + 0) * WH_BUF);
        const unsigned int* wh1 = (const unsigned int*)(wh + (cur * 2 + 1) * WH_BUF);
#pragma unroll
        for (int ks = 0; ks < 2; ks++) {
            int kc16 = ks * 16;
            unsigned int ahi[2][4], alo[2][4];
#pragma unroll
            for (int mt = 0; mt < 2; mt++) {
                int rb = wm * 32 + mt * 16 + r0;
                float2 p0 = *(const float2*)(qc + rb * QS_STRIDE + kc16 + cq);
                float2 p1 = *(const float2*)(qc + (rb + 8) * QS_STRIDE + kc16 + cq);
                float2 p2 = *(const float2*)(qc + rb * QS_STRIDE + kc16 + cq + 8);
                float2 p3 = *(const float2*)(qc + (rb + 8) * QS_STRIDE + kc16 + cq + 8);
                split_h2(p0, ahi[mt][0], alo[mt][0]);
                split_h2(p1, ahi[mt][1], alo[mt][1]);
                split_h2(p2, ahi[mt][2], alo[mt][2]);
                split_h2(p3, ahi[mt][3], alo[mt][3]);
            }
#pragma unroll
            for (int nt = 0; nt < 8; nt++) {
                int n = bn + nt * 8;
                int w0 = n * (WH_STRIDE / 2) + ks * 8 + bw;
                unsigned int bhi[2], blo[2];
                bhi[0] = wh0[w0];       bhi[1] = wh0[w0 + 4];
                blo[0] = wh1[w0];       blo[1] = wh1[w0 + 4];
#pragma unroll
                for (int mt = 0; mt < 2; mt++) {
                    mma16(c[mt][nt], ahi[mt], bhi);
                    mma16(c[mt][nt], ahi[mt], blo);
                    mma16(c[mt][nt], alo[mt], bhi);
                }
            }
        }
        cp_wait0();
        __syncthreads();
    }

    float* dst = g_qhp[ksp];
    int er = m0 + wm * 32 + (lane >> 2);
    int ec = wn * 64 + 2 * (lane & 3);
#pragma unroll
    for (int mt = 0; mt < 2; mt++) {
#pragma unroll
        for (int nt = 0; nt < 8; nt++) {
            float* p0 = dst + (size_t)(er + mt * 16) * HID + ec + nt * 8;
            float* p1 = dst + (size_t)(er + mt * 16 + 8) * HID + ec + nt * 8;
            *(float2*)p0 = make_float2(c[mt][nt][0], c[mt][nt][1]);
            *(float2*)p1 = make_float2(c[mt][nt][2], c[mt][nt][3]);
        }
    }
}

// ---- kernel 3: rel + top-k + gather. NBQ=2 queries/block, grid 2048 ----
__global__ __launch_bounds__(128) void k3_ctx(const float* __restrict__ query,
                                              const float* __restrict__ seg,
                                              const float* __restrict__ rb1,
                                              const float* __restrict__ rw2,
                                              const float* __restrict__ rb2,
                                              float* __restrict__ out) {
    int tid = threadIdx.x, lane = tid & 31, wrp = tid >> 5;
    int b0 = blockIdx.x * NBQ;

    __shared__ float s_score[NBQ][NSEG];
    __shared__ float s_w[NBQ][NSEG];
    __shared__ int   s_idx[NBQ][TOPK];
    __shared__ float s_wn[NBQ][TOPK];

    float qb[NBQ][4], rv[4];
#pragma unroll
    for (int j = 0; j < 4; j++) {
        int h = lane + 32 * j;
        rv[j] = rw2[h];
        float rb = rb1[h];
#pragma unroll
        for (int b = 0; b < NBQ; b++) {
            size_t idx = (size_t)(b0 + b) * HID + h;
            float q = 0.f;
#pragma unroll
            for (int s = 0; s < KSPLIT; s++) q += g_qhp[s][idx];
            qb[b][j] = q + rb;
        }
    }
    float rb2v = rb2[0];

    for (int n = wrp; n < NSEG; n += 4) {
        float sh0 = g_sh[n * HID + lane];
        float sh1 = g_sh[n * HID + 32 + lane];
        float sh2 = g_sh[n * HID + 64 + lane];
        float sh3 = g_sh[n * HID + 96 + lane];
        float s[NBQ];
#pragma unroll
        for (int b = 0; b < NBQ; b++) {
            s[b] = gelu_fast(qb[b][0] + sh0) * rv[0];
            s[b] = fmaf(gelu_fast(qb[b][1] + sh1), rv[1], s[b]);
            s[b] = fmaf(gelu_fast(qb[b][2] + sh2), rv[2], s[b]);
            s[b] = fmaf(gelu_fast(qb[b][3] + sh3), rv[3], s[b]);
        }
#pragma unroll
        for (int off = 16; off >= 1; off >>= 1)
#pragma unroll
            for (int b = 0; b < NBQ; b++) s[b] += __shfl_xor_sync(0xffffffffu, s[b], off);
        if (lane == 0) {
            float imp = g_imp[n], cs = g_cs[n];
#pragma unroll
            for (int b = 0; b < NBQ; b++) {
                float rel = sigmoid_f(s[b] + rb2v);
                s_score[b][n] = cs * rel;
                s_w[b][n]     = imp * rel;
            }
        }
    }
    __syncthreads();

    if (wrp < NBQ) {
        int b = wrp;
        float v0 = s_score[b][lane];
        float v1 = s_score[b][lane + 32];
        float v2 = s_score[b][lane + 64];
        float v3 = (lane + 96 < NSEG) ? s_score[b][lane + 96] : -INFINITY;
        float wsum = 0.f;
        for (int k = 0; k < TOPK; k++) {
            float bv = v0; int bj = 0;
            if (v1 > bv) { bv = v1; bj = 1; }
            if (v2 > bv) { bv = v2; bj = 2; }
            if (v3 > bv) { bv = v3; bj = 3; }
            int bi = lane + 32 * bj;
#pragma unroll
            for (int off = 16; off >= 1; off >>= 1) {
                float ov = __shfl_xor_sync(0xffffffffu, bv, off);
                int   oi = __shfl_xor_sync(0xffffffffu, bi, off);
                if (ov > bv || (ov == bv && oi < bi)) { bv = ov; bi = oi; }
            }
            if ((bi & 31) == lane) {
                int j = bi >> 5;
                if (j == 0) v0 = -INFINITY;
                else if (j == 1) v1 = -INFINITY;
                else if (j == 2) v2 = -INFINITY;
                else v3 = -INFINITY;
            }
            wsum += s_w[b][bi];
            if (lane == 0) s_idx[b][k] = bi;
        }
        __syncwarp();
        if (lane < TOPK) {
            int bi = s_idx[b][lane];
            s_wn[b][lane] = s_w[b][bi] / (wsum + 1e-8f);
        }
    }
    __syncthreads();

    for (int b = 0; b < NBQ; b++) {
        int bq = b0 + b;
        const float4* sp[TOPK];
        float wn[TOPK];
#pragma unroll
        for (int k = 0; k < TOPK; k++) {
            sp[k] = reinterpret_cast<const float4*>(seg + (size_t)s_idx[b][k] * DIM);
            wn[k] = s_wn[b][k];
        }
        const float4* q4 = reinterpret_cast<const float4*>(query + (size_t)bq * DIM);
        float4*       o4 = reinterpret_cast<float4*>(out + (size_t)bq * DIM);
        for (int t = tid; t < DIM / 4; t += 128) {
            float4 a = q4[t];
#pragma unroll
            for (int k = 0; k < TOPK; k++) {
                float4 sv = sp[k][t];
                a.x = fmaf(wn[k], sv.x, a.x);
                a.y = fmaf(wn[k], sv.y, a.y);
                a.z = fmaf(wn[k], sv.z, a.z);
                a.w = fmaf(wn[k], sv.w, a.w);
            }
            o4[t] = a;
        }
    }
}

extern "C" void kernel_launch(void* const* d_in, const int* in_sizes, int n_in,
                              void* d_out, int out_size) {
    const float* query     = (const float*)d_in[0];
    const float* seg       = (const float*)d_in[1];
    const int*   positions = (const int*)d_in[2];
    const float* iw1       = (const float*)d_in[3];
    const float* ib1       = (const float*)d_in[4];
    const float* ib2_      = (const float*)d_in[6];
    const float* iw2       = (const float*)d_in[5];
    const float* rw1       = (const float*)d_in[7];
    const float* rb1       = (const float*)d_in[8];
    const float* rw2       = (const float*)d_in[9];
    const float* rb2       = (const float*)d_in[10];
    float* out = (float*)d_out;

    cudaFuncSetAttribute(k2_mma, cudaFuncAttributeMaxDynamicSharedMemorySize, K2_SMEM);

    dim3 g1(NSLICE, NSEG / 10);
    k1a_part<<<g1, 128>>>(seg, iw1, rw1);
    k2_mma<<<32 * KSPLIT + NSEG, 256, K2_SMEM>>>(query, positions, ib1, iw2, ib2_);
    k3_ctx<<<BQ / NBQ, 128>>>(query, seg, rb1, rw2, rb2, out);
}

// round 16
// speedup vs baseline: 1.3746x; 1.3746x over previous
#include <cuda_runtime.h>
#include <cuda_fp16.h>
#include <stdint.h>
#include <math.h>

#define BQ   4096
#define NSEG 100
#define DIM  4096
#define HID  128
#define TOPK 10
#define NSLICE 64
#define DCH  (DIM / NSLICE)   /* 64 */
#define KSPLIT 8

__device__ float g_qhp[KSPLIT][BQ * HID];
__device__ float g_sh[NSEG * HID];
__device__ float g_imp[NSEG];
__device__ float g_cs[NSEG];
__device__ float g_p1[NSLICE * NSEG * HID];
__device__ float g_p2[NSLICE * NSEG * HID];
__device__ __align__(16) unsigned short g_wh0[HID * DIM];
__device__ __align__(16) unsigned short g_wh1[HID * DIM];

__device__ __forceinline__ float gelu_f(float x) {
    return 0.5f * x * (1.0f + erff(x * 0.70710678118654752440f));
}
__device__ __forceinline__ float gelu_fast(float x) {
    float z = 0.70710678118654752440f * x;
    float a = fabsf(z);
    float t = __fdividef(1.0f, fmaf(0.3275911f, a, 1.0f));
    float poly = t * fmaf(t, fmaf(t, fmaf(t, fmaf(t, 1.061405429f, -1.453152027f),
                                          1.421413741f), -0.284496736f), 0.254829592f);
    float e = __expf(-z * z);
    float erfz = copysignf(fmaf(-poly, e, 1.0f), z);
    return fmaf(0.5f * x, erfz, 0.5f * x);
}
__device__ __forceinline__ float sigmoid_f(float x) { return 1.0f / (1.0f + expf(-x)); }

__device__ __forceinline__ void cp16(unsigned int s, const void* g) {
    asm volatile("cp.async.cg.shared.global [%0], [%1], 16;" :: "r"(s), "l"(g));
}
__device__ __forceinline__ void cp_commit() { asm volatile("cp.async.commit_group;"); }
__device__ __forceinline__ void cp_wait0()  { asm volatile("cp.async.wait_group 0;"); }

__device__ __forceinline__ void mma16(float* c, const unsigned int* a, const unsigned int* b) {
    asm volatile(
        "mma.sync.aligned.m16n8k16.row.col.f32.f16.f16.f32 "
        "{%0,%1,%2,%3}, {%4,%5,%6,%7}, {%8,%9}, {%0,%1,%2,%3};"
        : "+f"(c[0]), "+f"(c[1]), "+f"(c[2]), "+f"(c[3])
        : "r"(a[0]), "r"(a[1]), "r"(a[2]), "r"(a[3]), "r"(b[0]), "r"(b[1]));
}
__device__ __forceinline__ void split_h2(float2 v, unsigned int& hi, unsigned int& lo) {
    __half2 h = __floats2half2_rn(v.x, v.y);
    float2 hf = __half22float2(h);
    __half2 l = __floats2half2_rn(v.x - hf.x, v.y - hf.y);
    hi = *(unsigned int*)&h;
    lo = *(unsigned int*)&l;
}
__device__ __forceinline__ unsigned short h_hi(float x, float& rem) {
    __half h = __float2half_rn(x);
    rem = x - __half2float(h);
    return *(unsigned short*)&h;
}

// ---- kernel 1a: segment partials + (by==0) weight transpose/split ----
// grid (NSLICE=64, 10), 128 threads.
__global__ __launch_bounds__(128) void k1a_part(const float* __restrict__ seg,
                                                const float* __restrict__ iw1,
                                                const float* __restrict__ rw1) {
    int h = threadIdx.x, d0 = blockIdx.x * DCH, n0 = blockIdx.y * 10;

    if (blockIdx.y == 0) {
        for (int k4 = 0; k4 < DCH; k4 += 4) {
            float r0, r1, r2, r3;
            unsigned short a0 = h_hi(rw1[(size_t)(d0 + k4 + 0) * HID + h], r0);
            unsigned short a1 = h_hi(rw1[(size_t)(d0 + k4 + 1) * HID + h], r1);
            unsigned short a2 = h_hi(rw1[(size_t)(d0 + k4 + 2) * HID + h], r2);
            unsigned short a3 = h_hi(rw1[(size_t)(d0 + k4 + 3) * HID + h], r3);
            float d;
            ushort4 hv = make_ushort4(a0, a1, a2, a3);
            ushort4 lv = make_ushort4(h_hi(r0, d), h_hi(r1, d), h_hi(r2, d), h_hi(r3, d));
            *(ushort4*)(&g_wh0[(size_t)h * DIM + d0 + k4]) = hv;
            *(ushort4*)(&g_wh1[(size_t)h * DIM + d0 + k4]) = lv;
        }
    }

    __shared__ float segs[10][DCH];
    for (int i = h; i < 10 * DCH; i += 128)
        segs[i / DCH][i % DCH] = seg[(size_t)(n0 + i / DCH) * DIM + d0 + (i % DCH)];
    __syncthreads();
    float a1[10], a2[10];
#pragma unroll
    for (int n = 0; n < 10; n++) { a1[n] = 0.f; a2[n] = 0.f; }
    const float* w1p = iw1 + (size_t)d0 * HID + h;
    const float* w2p = rw1 + (size_t)(DIM + d0) * HID + h;
#pragma unroll 4
    for (int dd = 0; dd < DCH; dd++) {
        float w1 = w1p[(size_t)dd * HID], w2 = w2p[(size_t)dd * HID];
#pragma unroll
        for (int n = 0; n < 10; n++) {
            a1[n] = fmaf(segs[n][dd], w1, a1[n]);
            a2[n] = fmaf(segs[n][dd], w2, a2[n]);
        }
    }
#pragma unroll
    for (int n = 0; n < 10; n++) {
        g_p1[(blockIdx.x * NSEG + n0 + n) * HID + h] = a1[n];
        g_p2[(blockIdx.x * NSEG + n0 + n) * HID + h] = a2[n];
    }
}

// ---- kernel 2: mma blocks 0..255 + k1b blocks 256..355 ----
#define QS_STRIDE 36
#define WH_STRIDE 40
#define QS_BUF (128 * QS_STRIDE)
#define WH_BUF (128 * WH_STRIDE)
#define K2_SMEM (2 * QS_BUF * 4 + 4 * WH_BUF * 2)
__global__ __launch_bounds__(256, 2) void k2_mma(const float* __restrict__ query,
                                                 const int* __restrict__ positions,
                                                 const float* __restrict__ ib1,
                                                 const float* __restrict__ iw2,
                                                 const float* __restrict__ ib2) {
    int tid = threadIdx.x, lane = tid & 31, wid = tid >> 5;

    if (blockIdx.x >= 256) {
        int n = blockIdx.x - 256;
        __shared__ float red[4];
        float t = 0.f;
        if (tid < 128) {
            int h = tid;
            float s1 = 0.f, s2 = 0.f;
#pragma unroll 16
            for (int s = 0; s < NSLICE; s++) {
                s1 += g_p1[(s * NSEG + n) * HID + h];
                s2 += g_p2[(s * NSEG + n) * HID + h];
            }
            g_sh[n * HID + h] = s2;
            t = gelu_f(s1 + ib1[h]) * iw2[h];
#pragma unroll
            for (int off = 16; off >= 1; off >>= 1) t += __shfl_xor_sync(0xffffffffu, t, off);
            if (lane == 0) red[wid] = t;
        }
        __syncthreads();
        if (tid == 0) {
            float imp = sigmoid_f(red[0] + red[1] + red[2] + red[3] + ib2[0]);
            g_imp[n] = imp;
            g_cs[n] = imp * (0.5f + 0.5f * powf(0.95f, (float)(NSEG - 1 - positions[n])));
        }
        return;
    }

    extern __shared__ float sm[];
    float* qs = sm;
    unsigned short* wh = (unsigned short*)(sm + 2 * QS_BUF);

    int wm = wid & 3, wn = wid >> 2;
    int m0 = (blockIdx.x & 31) * 128;
    int ksp = blockIdx.x >> 5;
    int kbase = ksp * (DIM / KSPLIT);

    unsigned int qs_b = (unsigned int)__cvta_generic_to_shared(qs);
    unsigned int wh_b = (unsigned int)__cvta_generic_to_shared(wh);

    float c[2][8][4];
#pragma unroll
    for (int mt = 0; mt < 2; mt++)
#pragma unroll
        for (int nt = 0; nt < 8; nt++)
#pragma unroll
            for (int p = 0; p < 4; p++) c[mt][nt][p] = 0.f;

    auto issue = [&](int buf, int kc) {
#pragma unroll
        for (int j = 0; j < 4; j++) {
            int i = tid + j * 256;
            int row = i >> 3, g = i & 7;
            cp16(qs_b + (unsigned int)(buf * QS_BUF * 4 + row * (QS_STRIDE * 4) + g * 16),
                 query + (size_t)(m0 + row) * DIM + kc + g * 4);
        }
#pragma unroll
        for (int j = 0; j < 2; j++) {
            int i = tid + j * 256;
            int n = i >> 2, g = i & 3;
            cp16(wh_b + (unsigned int)((buf * 2 + 0) * WH_BUF * 2 + n * (WH_STRIDE * 2) + g * 16),
                 g_wh0 + (size_t)n * DIM + kc + g * 8);
        }
#pragma unroll
        for (int j = 0; j < 2; j++) {
            int i = tid + j * 256;
            int n = i >> 2, g = i & 3;
            cp16(wh_b + (unsigned int)((buf * 2 + 1) * WH_BUF * 2 + n * (WH_STRIDE * 2) + g * 16),
                 g_wh1 + (size_t)n * DIM + kc + g * 8);
        }
        cp_commit();
    };

    issue(0, kbase);
    cp_wait0();
    __syncthreads();

    int r0 = lane >> 2;
    int cq = (lane & 3) * 2;
    int bn = wn * 64 + (lane >> 2);
    int bw = lane & 3;

    const int NCH = (DIM / KSPLIT) / 32;
    for (int ch = 0; ch < NCH; ch++) {
        int cur = ch & 1;
        if (ch + 1 < NCH) issue(cur ^ 1, kbase + (ch + 1) * 32);

        const float* qc = qs + cur * QS_BUF;
        const unsigned int* wh0 = (const unsigned int*)(wh + (cur * 2 + 0) * WH_BUF);
        const unsigned int* wh1 = (const unsigned int*)(wh + (cur * 2 + 1) * WH_BUF);
#pragma unroll
        for (int ks = 0; ks < 2; ks++) {
            int kc16 = ks * 16;
            unsigned int ahi[2][4], alo[2][4];
#pragma unroll
            for (int mt = 0; mt < 2; mt++) {
                int rb = wm * 32 + mt * 16 + r0;
                float2 p0 = *(const float2*)(qc + rb * QS_STRIDE + kc16 + cq);
                float2 p1 = *(const float2*)(qc + (rb + 8) * QS_STRIDE + kc16 + cq);
                float2 p2 = *(const float2*)(qc + rb * QS_STRIDE + kc16 + cq + 8);
                float2 p3 = *(const float2*)(qc + (rb + 8) * QS_STRIDE + kc16 + cq + 8);
                split_h2(p0, ahi[mt][0], alo[mt][0]);
                split_h2(p1, ahi[mt][1], alo[mt][1]);
                split_h2(p2, ahi[mt][2], alo[mt][2]);
                split_h2(p3, ahi[mt][3], alo[mt][3]);
            }
#pragma unroll
            for (int nt = 0; nt < 8; nt++) {
                int n = bn + nt * 8;
                int w0 = n * (WH_STRIDE / 2) + ks * 8 + bw;
                unsigned int bhi[2], blo[2];
                bhi[0] = wh0[w0];       bhi[1] = wh0[w0 + 4];
                blo[0] = wh1[w0];       blo[1] = wh1[w0 + 4];
#pragma unroll
                for (int mt = 0; mt < 2; mt++) {
                    mma16(c[mt][nt], ahi[mt], bhi);
                    mma16(c[mt][nt], ahi[mt], blo);
                    mma16(c[mt][nt], alo[mt], bhi);
                }
            }
        }
        cp_wait0();
        __syncthreads();
    }

    float* dst = g_qhp[ksp];
    int er = m0 + wm * 32 + (lane >> 2);
    int ec = wn * 64 + 2 * (lane & 3);
#pragma unroll
    for (int mt = 0; mt < 2; mt++) {
#pragma unroll
        for (int nt = 0; nt < 8; nt++) {
            float* p0 = dst + (size_t)(er + mt * 16) * HID + ec + nt * 8;
            float* p1 = dst + (size_t)(er + mt * 16 + 8) * HID + ec + nt * 8;
            *(float2*)p0 = make_float2(c[mt][nt][0], c[mt][nt][1]);
            *(float2*)p1 = make_float2(c[mt][nt][2], c[mt][nt][3]);
        }
    }
}

// ---- kernel 3: rel + top-k + gather. NB=4, 128 thr, pipelined sh loads ----
__global__ __launch_bounds__(128) void k3_ctx(const float* __restrict__ query,
                                              const float* __restrict__ seg,
                                              const float* __restrict__ rb1,
                                              const float* __restrict__ rw2,
                                              const float* __restrict__ rb2,
                                              float* __restrict__ out) {
    int tid = threadIdx.x, lane = tid & 31, wrp = tid >> 5;
    int b0 = blockIdx.x * 4;

    __shared__ float s_score[4][NSEG];
    __shared__ float s_w[4][NSEG];
    __shared__ int   s_idx[4][TOPK];
    __shared__ float s_wn[4][TOPK];

    float qb[4][4], rv[4];
#pragma unroll
    for (int j = 0; j < 4; j++) {
        int h = lane + 32 * j;
        rv[j] = rw2[h];
        float rb = rb1[h];
#pragma unroll
        for (int b = 0; b < 4; b++) {
            size_t idx = (size_t)(b0 + b) * HID + h;
            float q = 0.f;
#pragma unroll
            for (int s = 0; s < KSPLIT; s++) q += g_qhp[s][idx];
            qb[b][j] = q + rb;
        }
    }
    float rb2v = rb2[0];

    // software-pipelined score loop: prefetch sh(n+4) before computing sh(n)
    float sh0 = g_sh[wrp * HID + lane];
    float sh1 = g_sh[wrp * HID + 32 + lane];
    float sh2 = g_sh[wrp * HID + 64 + lane];
    float sh3 = g_sh[wrp * HID + 96 + lane];
    for (int n = wrp; n < NSEG; n += 4) {
        float c0 = sh0, c1 = sh1, c2 = sh2, c3 = sh3;
        int np = n + 4;
        if (np < NSEG) {
            sh0 = g_sh[np * HID + lane];
            sh1 = g_sh[np * HID + 32 + lane];
            sh2 = g_sh[np * HID + 64 + lane];
            sh3 = g_sh[np * HID + 96 + lane];
        }
        float s[4];
#pragma unroll
        for (int b = 0; b < 4; b++) {
            s[b] = gelu_fast(qb[b][0] + c0) * rv[0];
            s[b] = fmaf(gelu_fast(qb[b][1] + c1), rv[1], s[b]);
            s[b] = fmaf(gelu_fast(qb[b][2] + c2), rv[2], s[b]);
            s[b] = fmaf(gelu_fast(qb[b][3] + c3), rv[3], s[b]);
        }
#pragma unroll
        for (int off = 16; off >= 1; off >>= 1)
#pragma unroll
            for (int b = 0; b < 4; b++) s[b] += __shfl_xor_sync(0xffffffffu, s[b], off);
        if (lane == 0) {
            float imp = g_imp[n], cs = g_cs[n];
#pragma unroll
            for (int b = 0; b < 4; b++) {
                float rel = sigmoid_f(s[b] + rb2v);
                s_score[b][n] = cs * rel;
                s_w[b][n]     = imp * rel;
            }
        }
    }
    __syncthreads();

    {
        int b = wrp;
        float v0 = s_score[b][lane];
        float v1 = s_score[b][lane + 32];
        float v2 = s_score[b][lane + 64];
        float v3 = (lane + 96 < NSEG) ? s_score[b][lane + 96] : -INFINITY;
        float wsum = 0.f;
        for (int k = 0; k < TOPK; k++) {
            float bv = v0; int bj = 0;
            if (v1 > bv) { bv = v1; bj = 1; }
            if (v2 > bv) { bv = v2; bj = 2; }
            if (v3 > bv) { bv = v3; bj = 3; }
            int bi = lane + 32 * bj;
#pragma unroll
            for (int off = 16; off >= 1; off >>= 1) {
                float ov = __shfl_xor_sync(0xffffffffu, bv, off);
                int   oi = __shfl_xor_sync(0xffffffffu, bi, off);
                if (ov > bv || (ov == bv && oi < bi)) { bv = ov; bi = oi; }
            }
            if ((bi & 31) == lane) {
                int j = bi >> 5;
                if (j == 0) v0 = -INFINITY;
                else if (j == 1) v1 = -INFINITY;
                else if (j == 2) v2 = -INFINITY;
                else v3 = -INFINITY;
            }
            wsum += s_w[b][bi];
            if (lane == 0) s_idx[b][k] = bi;
        }
        __syncwarp();
        if (lane < TOPK) {
            int bi = s_idx[b][lane];
            s_wn[b][lane] = s_w[b][bi] / (wsum + 1e-8f);
        }
    }
    __syncthreads();

    for (int b = 0; b < 4; b++) {
        int bq = b0 + b;
        const float4* sp[TOPK];
        float wn[TOPK];
#pragma unroll
        for (int k = 0; k < TOPK; k++) {
            sp[k] = reinterpret_cast<const float4*>(seg + (size_t)s_idx[b][k] * DIM);
            wn[k] = s_wn[b][k];
        }
        const float4* q4 = reinterpret_cast<const float4*>(query + (size_t)bq * DIM);
        float4*       o4 = reinterpret_cast<float4*>(out + (size_t)bq * DIM);
        for (int t = tid; t < DIM / 4; t += 128) {
            float4 a = q4[t];
#pragma unroll
            for (int k = 0; k < TOPK; k++) {
                float4 sv = sp[k][t];
                a.x = fmaf(wn[k], sv.x, a.x);
                a.y = fmaf(wn[k], sv.y, a.y);
                a.z = fmaf(wn[k], sv.z, a.z);
                a.w = fmaf(wn[k], sv.w, a.w);
            }
            o4[t] = a;
        }
    }
}

extern "C" void kernel_launch(void* const* d_in, const int* in_sizes, int n_in,
                              void* d_out, int out_size) {
    const float* query     = (const float*)d_in[0];
    const float* seg       = (const float*)d_in[1];
    const int*   positions = (const int*)d_in[2];
    const float* iw1       = (const float*)d_in[3];
    const float* ib1       = (const float*)d_in[4];
    const float* iw2       = (const float*)d_in[5];
    const float* ib2       = (const float*)d_in[6];
    const float* rw1       = (const float*)d_in[7];
    const float* rb1       = (const float*)d_in[8];
    const float* rw2       = (const float*)d_in[9];
    const float* rb2       = (const float*)d_in[10];
    float* out = (float*)d_out;

    cudaFuncSetAttribute(k2_mma, cudaFuncAttributeMaxDynamicSharedMemorySize, K2_SMEM);

    dim3 g1(NSLICE, NSEG / 10);
    k1a_part<<<g1, 128>>>(seg, iw1, rw1);
    k2_mma<<<32 * KSPLIT + NSEG, 256, K2_SMEM>>>(query, positions, ib1, iw2, ib2);
    k3_ctx<<<BQ / 4, 128>>>(query, seg, rb1, rw2, rb2, out);
}

// round 17
// speedup vs baseline: 1.4263x; 1.0376x over previous
#include <cuda_runtime.h>
#include <cuda_fp16.h>
#include <stdint.h>
#include <math.h>

#define BQ   4096
#define NSEG 100
#define DIM  4096
#define HID  128
#define TOPK 10
#define NSLICE 64
#define DCH  (DIM / NSLICE)   /* 64 */
#define KSPLIT 8

__device__ float g_qhp[KSPLIT][BQ * HID];
__device__ float g_sh[NSEG * HID];
__device__ float g_imp[NSEG];
__device__ float g_cs[NSEG];
__device__ float g_p1[NSLICE * NSEG * HID];
__device__ float g_p2[NSLICE * NSEG * HID];
__device__ __align__(16) unsigned short g_wh0[HID * DIM];
__device__ __align__(16) unsigned short g_wh1[HID * DIM];
__device__ int   g_tidx[BQ * TOPK];
__device__ float g_tw[BQ * TOPK];

__device__ __forceinline__ float gelu_f(float x) {
    return 0.5f * x * (1.0f + erff(x * 0.70710678118654752440f));
}
__device__ __forceinline__ float gelu_fast(float x) {
    float z = 0.70710678118654752440f * x;
    float a = fabsf(z);
    float t = __fdividef(1.0f, fmaf(0.3275911f, a, 1.0f));
    float poly = t * fmaf(t, fmaf(t, fmaf(t, fmaf(t, 1.061405429f, -1.453152027f),
                                          1.421413741f), -0.284496736f), 0.254829592f);
    float e = __expf(-z * z);
    float erfz = copysignf(fmaf(-poly, e, 1.0f), z);
    return fmaf(0.5f * x, erfz, 0.5f * x);
}
__device__ __forceinline__ float sigmoid_f(float x) { return 1.0f / (1.0f + expf(-x)); }

__device__ __forceinline__ void cp16(unsigned int s, const void* g) {
    asm volatile("cp.async.cg.shared.global [%0], [%1], 16;" :: "r"(s), "l"(g));
}
__device__ __forceinline__ void cp_commit() { asm volatile("cp.async.commit_group;"); }
__device__ __forceinline__ void cp_wait0()  { asm volatile("cp.async.wait_group 0;"); }

__device__ __forceinline__ void mma16(float* c, const unsigned int* a, const unsigned int* b) {
    asm volatile(
        "mma.sync.aligned.m16n8k16.row.col.f32.f16.f16.f32 "
        "{%0,%1,%2,%3}, {%4,%5,%6,%7}, {%8,%9}, {%0,%1,%2,%3};"
        : "+f"(c[0]), "+f"(c[1]), "+f"(c[2]), "+f"(c[3])
        : "r"(a[0]), "r"(a[1]), "r"(a[2]), "r"(a[3]), "r"(b[0]), "r"(b[1]));
}
__device__ __forceinline__ void split_h2(float2 v, unsigned int& hi, unsigned int& lo) {
    __half2 h = __floats2half2_rn(v.x, v.y);
    float2 hf = __half22float2(h);
    __half2 l = __floats2half2_rn(v.x - hf.x, v.y - hf.y);
    hi = *(unsigned int*)&h;
    lo = *(unsigned int*)&l;
}
__device__ __forceinline__ unsigned short h_hi(float x, float& rem) {
    __half h = __float2half_rn(x);
    rem = x - __half2float(h);
    return *(unsigned short*)&h;
}

// ---- kernel 1a: segment partials + (by==0) weight transpose/split ----
__global__ __launch_bounds__(128) void k1a_part(const float* __restrict__ seg,
                                                const float* __restrict__ iw1,
                                                const float* __restrict__ rw1) {
    int h = threadIdx.x, d0 = blockIdx.x * DCH, n0 = blockIdx.y * 10;

    if (blockIdx.y == 0) {
        for (int k4 = 0; k4 < DCH; k4 += 4) {
            float r0, r1, r2, r3;
            unsigned short a0 = h_hi(rw1[(size_t)(d0 + k4 + 0) * HID + h], r0);
            unsigned short a1 = h_hi(rw1[(size_t)(d0 + k4 + 1) * HID + h], r1);
            unsigned short a2 = h_hi(rw1[(size_t)(d0 + k4 + 2) * HID + h], r2);
            unsigned short a3 = h_hi(rw1[(size_t)(d0 + k4 + 3) * HID + h], r3);
            float d;
            ushort4 hv = make_ushort4(a0, a1, a2, a3);
            ushort4 lv = make_ushort4(h_hi(r0, d), h_hi(r1, d), h_hi(r2, d), h_hi(r3, d));
            *(ushort4*)(&g_wh0[(size_t)h * DIM + d0 + k4]) = hv;
            *(ushort4*)(&g_wh1[(size_t)h * DIM + d0 + k4]) = lv;
        }
    }

    __shared__ float segs[10][DCH];
    for (int i = h; i < 10 * DCH; i += 128)
        segs[i / DCH][i % DCH] = seg[(size_t)(n0 + i / DCH) * DIM + d0 + (i % DCH)];
    __syncthreads();
    float a1[10], a2[10];
#pragma unroll
    for (int n = 0; n < 10; n++) { a1[n] = 0.f; a2[n] = 0.f; }
    const float* w1p = iw1 + (size_t)d0 * HID + h;
    const float* w2p = rw1 + (size_t)(DIM + d0) * HID + h;
#pragma unroll 4
    for (int dd = 0; dd < DCH; dd++) {
        float w1 = w1p[(size_t)dd * HID], w2 = w2p[(size_t)dd * HID];
#pragma unroll
        for (int n = 0; n < 10; n++) {
            a1[n] = fmaf(segs[n][dd], w1, a1[n]);
            a2[n] = fmaf(segs[n][dd], w2, a2[n]);
        }
    }
#pragma unroll
    for (int n = 0; n < 10; n++) {
        g_p1[(blockIdx.x * NSEG + n0 + n) * HID + h] = a1[n];
        g_p2[(blockIdx.x * NSEG + n0 + n) * HID + h] = a2[n];
    }
}

// ---- kernel 2: mma blocks 0..255 + k1b blocks 256..355 (frozen) ----
#define QS_STRIDE 36
#define WH_STRIDE 40
#define QS_BUF (128 * QS_STRIDE)
#define WH_BUF (128 * WH_STRIDE)
#define K2_SMEM (2 * QS_BUF * 4 + 4 * WH_BUF * 2)
__global__ __launch_bounds__(256, 2) void k2_mma(const float* __restrict__ query,
                                                 const int* __restrict__ positions,
                                                 const float* __restrict__ ib1,
                                                 const float* __restrict__ iw2,
                                                 const float* __restrict__ ib2) {
    int tid = threadIdx.x, lane = tid & 31, wid = tid >> 5;

    if (blockIdx.x >= 256) {
        int n = blockIdx.x - 256;
        __shared__ float red[4];
        float t = 0.f;
        if (tid < 128) {
            int h = tid;
            float s1 = 0.f, s2 = 0.f;
#pragma unroll 16
            for (int s = 0; s < NSLICE; s++) {
                s1 += g_p1[(s * NSEG + n) * HID + h];
                s2 += g_p2[(s * NSEG + n) * HID + h];
            }
            g_sh[n * HID + h] = s2;
            t = gelu_f(s1 + ib1[h]) * iw2[h];
#pragma unroll
            for (int off = 16; off >= 1; off >>= 1) t += __shfl_xor_sync(0xffffffffu, t, off);
            if (lane == 0) red[wid] = t;
        }
        __syncthreads();
        if (tid == 0) {
            float imp = sigmoid_f(red[0] + red[1] + red[2] + red[3] + ib2[0]);
            g_imp[n] = imp;
            g_cs[n] = imp * (0.5f + 0.5f * powf(0.95f, (float)(NSEG - 1 - positions[n])));
        }
        return;
    }

    extern __shared__ float sm[];
    float* qs = sm;
    unsigned short* wh = (unsigned short*)(sm + 2 * QS_BUF);

    int wm = wid & 3, wn = wid >> 2;
    int m0 = (blockIdx.x & 31) * 128;
    int ksp = blockIdx.x >> 5;
    int kbase = ksp * (DIM / KSPLIT);

    unsigned int qs_b = (unsigned int)__cvta_generic_to_shared(qs);
    unsigned int wh_b = (unsigned int)__cvta_generic_to_shared(wh);

    float c[2][8][4];
#pragma unroll
    for (int mt = 0; mt < 2; mt++)
#pragma unroll
        for (int nt = 0; nt < 8; nt++)
#pragma unroll
            for (int p = 0; p < 4; p++) c[mt][nt][p] = 0.f;

    auto issue = [&](int buf, int kc) {
#pragma unroll
        for (int j = 0; j < 4; j++) {
            int i = tid + j * 256;
            int row = i >> 3, g = i & 7;
            cp16(qs_b + (unsigned int)(buf * QS_BUF * 4 + row * (QS_STRIDE * 4) + g * 16),
                 query + (size_t)(m0 + row) * DIM + kc + g * 4);
        }
#pragma unroll
        for (int j = 0; j < 2; j++) {
            int i = tid + j * 256;
            int n = i >> 2, g = i & 3;
            cp16(wh_b + (unsigned int)((buf * 2 + 0) * WH_BUF * 2 + n * (WH_STRIDE * 2) + g * 16),
                 g_wh0 + (size_t)n * DIM + kc + g * 8);
        }
#pragma unroll
        for (int j = 0; j < 2; j++) {
            int i = tid + j * 256;
            int n = i >> 2, g = i & 3;
            cp16(wh_b + (unsigned int)((buf * 2 + 1) * WH_BUF * 2 + n * (WH_STRIDE * 2) + g * 16),
                 g_wh1 + (size_t)n * DIM + kc + g * 8);
        }
        cp_commit();
    };

    issue(0, kbase);
    cp_wait0();
    __syncthreads();

    int r0 = lane >> 2;
    int cq = (lane & 3) * 2;
    int bn = wn * 64 + (lane >> 2);
    int bw = lane & 3;

    const int NCH = (DIM / KSPLIT) / 32;
    for (int ch = 0; ch < NCH; ch++) {
        int cur = ch & 1;
        if (ch + 1 < NCH) issue(cur ^ 1, kbase + (ch + 1) * 32);

        const float* qc = qs + cur * QS_BUF;
        const unsigned int* wh0 = (const unsigned int*)(wh + (cur * 2 + 0) * WH_BUF);
        const unsigned int* wh1 = (const unsigned int*)(wh + (cur * 2 + 1) * WH_BUF);
#pragma unroll
        for (int ks = 0; ks < 2; ks++) {
            int kc16 = ks * 16;
            unsigned int ahi[2][4], alo[2][4];
#pragma unroll
            for (int mt = 0; mt < 2; mt++) {
                int rb = wm * 32 + mt * 16 + r0;
                float2 p0 = *(const float2*)(qc + rb * QS_STRIDE + kc16 + cq);
                float2 p1 = *(const float2*)(qc + (rb + 8) * QS_STRIDE + kc16 + cq);
                float2 p2 = *(const float2*)(qc + rb * QS_STRIDE + kc16 + cq + 8);
                float2 p3 = *(const float2*)(qc + (rb + 8) * QS_STRIDE + kc16 + cq + 8);
                split_h2(p0, ahi[mt][0], alo[mt][0]);
                split_h2(p1, ahi[mt][1], alo[mt][1]);
                split_h2(p2, ahi[mt][2], alo[mt][2]);
                split_h2(p3, ahi[mt][3], alo[mt][3]);
            }
#pragma unroll
            for (int nt = 0; nt < 8; nt++) {
                int n = bn + nt * 8;
                int w0 = n * (WH_STRIDE / 2) + ks * 8 + bw;
                unsigned int bhi[2], blo[2];
                bhi[0] = wh0[w0];       bhi[1] = wh0[w0 + 4];
                blo[0] = wh1[w0];       blo[1] = wh1[w0 + 4];
#pragma unroll
                for (int mt = 0; mt < 2; mt++) {
                    mma16(c[mt][nt], ahi[mt], bhi);
                    mma16(c[mt][nt], ahi[mt], blo);
                    mma16(c[mt][nt], alo[mt], bhi);
                }
            }
        }
        cp_wait0();
        __syncthreads();
    }

    float* dst = g_qhp[ksp];
    int er = m0 + wm * 32 + (lane >> 2);
    int ec = wn * 64 + 2 * (lane & 3);
#pragma unroll
    for (int mt = 0; mt < 2; mt++) {
#pragma unroll
        for (int nt = 0; nt < 8; nt++) {
            float* p0 = dst + (size_t)(er + mt * 16) * HID + ec + nt * 8;
            float* p1 = dst + (size_t)(er + mt * 16 + 8) * HID + ec + nt * 8;
            *(float2*)p0 = make_float2(c[mt][nt][0], c[mt][nt][1]);
            *(float2*)p1 = make_float2(c[mt][nt][2], c[mt][nt][3]);
        }
    }
}

// ---- kernel 3a: rel + top-k -> global (idx, weight). NB=4, 128 thr ----
__global__ __launch_bounds__(128) void k3a_score(const float* __restrict__ rb1,
                                                 const float* __restrict__ rw2,
                                                 const float* __restrict__ rb2) {
    int tid = threadIdx.x, lane = tid & 31, wrp = tid >> 5;
    int b0 = blockIdx.x * 4;

    __shared__ float s_score[4][NSEG];
    __shared__ float s_w[4][NSEG];
    __shared__ int   s_idx[4][TOPK];

    float qb[4][4], rv[4];
#pragma unroll
    for (int j = 0; j < 4; j++) {
        int h = lane + 32 * j;
        rv[j] = rw2[h];
        float rb = rb1[h];
#pragma unroll
        for (int b = 0; b < 4; b++) {
            size_t idx = (size_t)(b0 + b) * HID + h;
            float q = 0.f;
#pragma unroll
            for (int s = 0; s < KSPLIT; s++) q += g_qhp[s][idx];
            qb[b][j] = q + rb;
        }
    }
    float rb2v = rb2[0];

    for (int n = wrp; n < NSEG; n += 4) {
        float sh0 = g_sh[n * HID + lane];
        float sh1 = g_sh[n * HID + 32 + lane];
        float sh2 = g_sh[n * HID + 64 + lane];
        float sh3 = g_sh[n * HID + 96 + lane];
        float s[4];
#pragma unroll
        for (int b = 0; b < 4; b++) {
            s[b] = gelu_fast(qb[b][0] + sh0) * rv[0];
            s[b] = fmaf(gelu_fast(qb[b][1] + sh1), rv[1], s[b]);
            s[b] = fmaf(gelu_fast(qb[b][2] + sh2), rv[2], s[b]);
            s[b] = fmaf(gelu_fast(qb[b][3] + sh3), rv[3], s[b]);
        }
#pragma unroll
        for (int off = 16; off >= 1; off >>= 1)
#pragma unroll
            for (int b = 0; b < 4; b++) s[b] += __shfl_xor_sync(0xffffffffu, s[b], off);
        if (lane == 0) {
            float imp = g_imp[n], cs = g_cs[n];
#pragma unroll
            for (int b = 0; b < 4; b++) {
                float rel = sigmoid_f(s[b] + rb2v);
                s_score[b][n] = cs * rel;
                s_w[b][n]     = imp * rel;
            }
        }
    }
    __syncthreads();

    {
        int b = wrp;
        float v0 = s_score[b][lane];
        float v1 = s_score[b][lane + 32];
        float v2 = s_score[b][lane + 64];
        float v3 = (lane + 96 < NSEG) ? s_score[b][lane + 96] : -INFINITY;
        float wsum = 0.f;
        for (int k = 0; k < TOPK; k++) {
            float bv = v0; int bj = 0;
            if (v1 > bv) { bv = v1; bj = 1; }
            if (v2 > bv) { bv = v2; bj = 2; }
            if (v3 > bv) { bv = v3; bj = 3; }
            int bi = lane + 32 * bj;
#pragma unroll
            for (int off = 16; off >= 1; off >>= 1) {
                float ov = __shfl_xor_sync(0xffffffffu, bv, off);
                int   oi = __shfl_xor_sync(0xffffffffu, bi, off);
                if (ov > bv || (ov == bv && oi < bi)) { bv = ov; bi = oi; }
            }
            if ((bi & 31) == lane) {
                int j = bi >> 5;
                if (j == 0) v0 = -INFINITY;
                else if (j == 1) v1 = -INFINITY;
                else if (j == 2) v2 = -INFINITY;
                else v3 = -INFINITY;
            }
            wsum += s_w[b][bi];
            if (lane == 0) s_idx[b][k] = bi;
        }
        __syncwarp();
        if (lane < TOPK) {
            int bi = s_idx[b][lane];
            g_tidx[(b0 + b) * TOPK + lane] = bi;
            g_tw[(b0 + b) * TOPK + lane]   = s_w[b][bi] / (wsum + 1e-8f);
        }
    }
}

// ---- kernel 3b: gather. 1 query/block, 256 thr, MLP-10 row loads ----
__global__ __launch_bounds__(256) void k3b_gather(const float* __restrict__ query,
                                                  const float* __restrict__ seg,
                                                  float* __restrict__ out) {
    int tid = threadIdx.x;
    int b = blockIdx.x;

    __shared__ int   sidx[TOPK];
    __shared__ float swn[TOPK];
    if (tid < TOPK) {
        sidx[tid] = g_tidx[b * TOPK + tid];
        swn[tid]  = g_tw[b * TOPK + tid];
    }
    __syncthreads();

    const float4* sp[TOPK];
    float wn[TOPK];
#pragma unroll
    for (int k = 0; k < TOPK; k++) {
        sp[k] = reinterpret_cast<const float4*>(seg + (size_t)sidx[k] * DIM);
        wn[k] = swn[k];
    }
    const float4* q4 = reinterpret_cast<const float4*>(query + (size_t)b * DIM);
    float4*       o4 = reinterpret_cast<float4*>(out + (size_t)b * DIM);

#pragma unroll
    for (int j = 0; j < 4; j++) {
        int t = tid + j * 256;
        float4 a = q4[t];
        float4 r[TOPK];
#pragma unroll
        for (int k = 0; k < TOPK; k++) r[k] = sp[k][t];
#pragma unroll
        for (int k = 0; k < TOPK; k++) {
            a.x = fmaf(wn[k], r[k].x, a.x);
            a.y = fmaf(wn[k], r[k].y, a.y);
            a.z = fmaf(wn[k], r[k].z, a.z);
            a.w = fmaf(wn[k], r[k].w, a.w);
        }
        o4[t] = a;
    }
}

extern "C" void kernel_launch(void* const* d_in, const int* in_sizes, int n_in,
                              void* d_out, int out_size) {
    const float* query     = (const float*)d_in[0];
    const float* seg       = (const float*)d_in[1];
    const int*   positions = (const int*)d_in[2];
    const float* iw1       = (const float*)d_in[3];
    const float* ib1       = (const float*)d_in[4];
    const float* iw2       = (const float*)d_in[5];
    const float* ib2       = (const float*)d_in[6];
    const float* rw1       = (const float*)d_in[7];
    const float* rb1       = (const float*)d_in[8];
    const float* rw2       = (const float*)d_in[9];
    const float* rb2       = (const float*)d_in[10];
    float* out = (float*)d_out;

    cudaFuncSetAttribute(k2_mma, cudaFuncAttributeMaxDynamicSharedMemorySize, K2_SMEM);

    dim3 g1(NSLICE, NSEG / 10);
    k1a_part<<<g1, 128>>>(seg, iw1, rw1);
    k2_mma<<<32 * KSPLIT + NSEG, 256, K2_SMEM>>>(query, positions, ib1, iw2, ib2);
    k3a_score<<<BQ / 4, 128>>>(rb1, rw2, rb2);
    k3b_gather<<<BQ, 256>>>(query, seg, out);
}